// round 8
// baseline (speedup 1.0000x reference)
#include <cuda_runtime.h>
#include <cuda_fp16.h>

#define N_ANG 720
#define N_DET 1024
#define HIMG 512
#define WIMG 512
#define KSZ 11
#define NB 8

// Filtered sinogram, fp16, layout [angle][det_bin][batch0..7] -> 16B per bin.
__device__ __align__(16) __half g_h[N_ANG * N_DET * NB];

// ---------------------------------------------------------------------------
// Stage 1: causal K=11 cross-correlation. One thread = (angle a, 4 consecutive
// detector bins), all 8 batches.
// ---------------------------------------------------------------------------
__global__ void __launch_bounds__(256) conv_kernel(const float* __restrict__ x,
                                                   const float* __restrict__ w) {
    int tx = threadIdx.x;        // detector quad index 0..255
    int a  = blockIdx.x;         // angle

    float wk[KSZ];
#pragma unroll
    for (int k = 0; k < KSZ; ++k) wk[k] = __ldg(w + k);

    uint4 out[4];

#pragma unroll
    for (int bp = 0; bp < 4; ++bp) {          // batch pairs
        float acc[2][4];
#pragma unroll
        for (int s = 0; s < 2; ++s) {
            int b = bp * 2 + s;
            const float4* xb = reinterpret_cast<const float4*>(
                x + (size_t)b * (N_ANG * N_DET) + (size_t)a * N_DET);
            float win[16];
#pragma unroll
            for (int q = 0; q < 4; ++q) {
                int qi = tx - 3 + q;
                float4 v;
                if (qi >= 0) v = __ldg(xb + qi);
                else         v = make_float4(0.f, 0.f, 0.f, 0.f);
                win[q * 4 + 0] = v.x; win[q * 4 + 1] = v.y;
                win[q * 4 + 2] = v.z; win[q * 4 + 3] = v.w;
            }
#pragma unroll
            for (int di = 0; di < 4; ++di) {
                float acc_ = 0.f;
#pragma unroll
                for (int k = 0; k < KSZ; ++k)
                    acc_ = fmaf(wk[k], win[di + k + 2], acc_);
                acc[s][di] = acc_;
            }
        }
#pragma unroll
        for (int di = 0; di < 4; ++di) {
            __half2 h = __floats2half2_rn(acc[0][di], acc[1][di]);
            reinterpret_cast<unsigned int*>(&out[di])[bp] =
                *reinterpret_cast<unsigned int*>(&h);
        }
    }

    uint4* gp = reinterpret_cast<uint4*>(g_h) + ((size_t)a << 10) + (tx << 2);
#pragma unroll
    for (int di = 0; di < 4; ++di) gp[di] = out[di];
}

// ---------------------------------------------------------------------------
// Stage 2: backprojection, PIXEL-PAIR version. One thread = two adjacent
// j-pixels, all 8 batches. u(j+1) = u(j) + sin(th), sin(th) in (0,1] ->
// both pixels' bins lie in {base, base+1, base+2}: 3 LDG.128 instead of 4
// (24B/pixel-angle instead of 32B -> L1 data-path floor 168us -> 126us).
// Pixel0: standard 2-tap. Pixel1: branch-free 3-point weights
//   g  = u1 - base               (exact fp32)
//   w0 = max(1-g,0), w2 = max(g-1,0), w1 = 1-w0-w2
// which reproduce the reference (1-f1, f1) exactly in fp32.
// Split half2 accumulators per pixel, flushed to fp32 every 8 angles.
// ---------------------------------------------------------------------------
__global__ void __launch_bounds__(256, 3) bp_kernel(float* __restrict__ out) {
    __shared__ float2 trig[N_ANG];        // (cos/DS, sin/DS)

    const float DTH = 3.14159265358979323846f / (float)N_ANG;
    const float DX  = 2.0f / (float)HIMG;
    const float INV_DS = (float)N_DET / 4.0f;   // 256

    for (int a = threadIdx.x; a < N_ANG; a += blockDim.x) {
        float th = ((float)a + 0.5f) * DTH;
        float s, c;
        sincosf(th, &s, &c);
        trig[a] = make_float2(c * INV_DS, s * INV_DS);
    }
    __syncthreads();

    int tx = threadIdx.x;
    int j0 = ((blockIdx.x << 3) + (tx & 7)) << 1;   // even j of the pair
    int i  = (blockIdx.y << 5) + (tx >> 3);
    float xc  = fmaf((float)i  + 0.5f, DX, -1.0f);
    float yc0 = fmaf((float)j0 + 0.5f, DX, -1.0f);
    float yc1 = yc0 + DX;

    float fa[16];                        // [pixel0 b0..7, pixel1 b0..7]
#pragma unroll
    for (int b = 0; b < 16; ++b) fa[b] = 0.f;

    const char* gbase = reinterpret_cast<const char*>(g_h);
    const __half2 one2  = __float2half2_rn(1.0f);
    const __half2 zero2 = __float2half2_rn(0.0f);

#pragma unroll 1
    for (int a0 = 0; a0 < N_ANG; a0 += 8) {
        // pixel0 accumulators (f / 1-f split), pixel1 accumulators (X: w0*b0+w2*b2, Y: w1*b1)
        __half2 aF0 = zero2, aF1 = zero2, aF2 = zero2, aF3 = zero2;
        __half2 aL0 = zero2, aL1 = zero2, aL2 = zero2, aL3 = zero2;
        __half2 aX0 = zero2, aX1 = zero2, aX2 = zero2, aX3 = zero2;
        __half2 aY0 = zero2, aY1 = zero2, aY2 = zero2, aY3 = zero2;

#pragma unroll
        for (int k = 0; k < 8; ++k) {
            int a = a0 + k;
            float2 cs = trig[a];
            float u0 = fmaf(xc, cs.x, fmaf(yc0, cs.y, 511.5f));
            float u1 = fmaf(xc, cs.x, fmaf(yc1, cs.y, 511.5f));
            float t  = __fadd_rd(u0, 8388608.0f);          // 2^23, round-down
            float fi = t - 8388608.0f;                      // exact floor(u0)
            float f0 = u0 - fi;                             // exact, [0,1)
            float g  = u1 - fi;                             // exact, [f0, 2)
            unsigned bits = __float_as_uint(t);
            unsigned off  = (bits << 9) >> 5;               // base * 16 bytes

            const uint4* p = reinterpret_cast<const uint4*>(
                gbase + ((size_t)a << 14) + off);
            uint4 b0 = __ldg(p);        // bin base
            uint4 b1 = __ldg(p + 1);    // bin base+1
            uint4 b2 = __ldg(p + 2);    // bin base+2

            float gm1 = g - 1.0f;
            float w0s = fmaxf(-gm1, 0.0f);                  // max(1-g,0)
            float w2s = fmaxf( gm1, 0.0f);                  // max(g-1,0)
            float w1s = 1.0f - w0s - w2s;

            __half2 f2   = __float2half2_rn(f0);
            __half2 omf2 = __hsub2(one2, f2);
            __half2 w0h  = __float2half2_rn(w0s);
            __half2 w1h  = __float2half2_rn(w1s);
            __half2 w2h  = __float2half2_rn(w2s);

            // pixel0: (1-f0)*b0 + f0*b1
            aF0 = __hfma2(f2,   *reinterpret_cast<__half2*>(&b1.x), aF0);
            aL0 = __hfma2(omf2, *reinterpret_cast<__half2*>(&b0.x), aL0);
            aF1 = __hfma2(f2,   *reinterpret_cast<__half2*>(&b1.y), aF1);
            aL1 = __hfma2(omf2, *reinterpret_cast<__half2*>(&b0.y), aL1);
            aF2 = __hfma2(f2,   *reinterpret_cast<__half2*>(&b1.z), aF2);
            aL2 = __hfma2(omf2, *reinterpret_cast<__half2*>(&b0.z), aL2);
            aF3 = __hfma2(f2,   *reinterpret_cast<__half2*>(&b1.w), aF3);
            aL3 = __hfma2(omf2, *reinterpret_cast<__half2*>(&b0.w), aL3);

            // pixel1: w0*b0 + w1*b1 + w2*b2
            aX0 = __hfma2(w0h, *reinterpret_cast<__half2*>(&b0.x),
                  __hfma2(w2h, *reinterpret_cast<__half2*>(&b2.x), aX0));
            aY0 = __hfma2(w1h, *reinterpret_cast<__half2*>(&b1.x), aY0);
            aX1 = __hfma2(w0h, *reinterpret_cast<__half2*>(&b0.y),
                  __hfma2(w2h, *reinterpret_cast<__half2*>(&b2.y), aX1));
            aY1 = __hfma2(w1h, *reinterpret_cast<__half2*>(&b1.y), aY1);
            aX2 = __hfma2(w0h, *reinterpret_cast<__half2*>(&b0.z),
                  __hfma2(w2h, *reinterpret_cast<__half2*>(&b2.z), aX2));
            aY2 = __hfma2(w1h, *reinterpret_cast<__half2*>(&b1.z), aY2);
            aX3 = __hfma2(w0h, *reinterpret_cast<__half2*>(&b0.w),
                  __hfma2(w2h, *reinterpret_cast<__half2*>(&b2.w), aX3));
            aY3 = __hfma2(w1h, *reinterpret_cast<__half2*>(&b1.w), aY3);
        }

        float2 v;
        __half2 s;
        s = __hadd2(aF0, aL0); v = __half22float2(s); fa[0]  += v.x; fa[1]  += v.y;
        s = __hadd2(aF1, aL1); v = __half22float2(s); fa[2]  += v.x; fa[3]  += v.y;
        s = __hadd2(aF2, aL2); v = __half22float2(s); fa[4]  += v.x; fa[5]  += v.y;
        s = __hadd2(aF3, aL3); v = __half22float2(s); fa[6]  += v.x; fa[7]  += v.y;
        s = __hadd2(aX0, aY0); v = __half22float2(s); fa[8]  += v.x; fa[9]  += v.y;
        s = __hadd2(aX1, aY1); v = __half22float2(s); fa[10] += v.x; fa[11] += v.y;
        s = __hadd2(aX2, aY2); v = __half22float2(s); fa[12] += v.x; fa[13] += v.y;
        s = __hadd2(aX3, aY3); v = __half22float2(s); fa[14] += v.x; fa[15] += v.y;
    }

    int p0 = i * WIMG + j0;
#pragma unroll
    for (int b = 0; b < NB; ++b) {
        out[b * (HIMG * WIMG) + p0]     = fa[b]     * DTH;
        out[b * (HIMG * WIMG) + p0 + 1] = fa[8 + b] * DTH;
    }
}

// ---------------------------------------------------------------------------
extern "C" void kernel_launch(void* const* d_in, const int* in_sizes, int n_in,
                              void* d_out, int out_size) {
    const float* x = (const float*)d_in[0];   // [8,1,720,1024]
    const float* w = (const float*)d_in[1];   // [1,1,1,11]
    float* out = (float*)d_out;               // [8,1,512,512]

    conv_kernel<<<N_ANG, 256>>>(x, w);
    dim3 grid(WIMG / 16, HIMG / 32);          // (32, 16) = 512 CTAs
    bp_kernel<<<grid, 256>>>(out);
}